// round 5
// baseline (speedup 1.0000x reference)
#include <cuda_runtime.h>
#include <math.h>
#include <stdint.h>

#define B_ 16
#define T_ 2048
#define C_ 512
#define H_ 64

// Scratch for projected q,k,v (__device__ globals = allowed scratch path)
__device__ float g_q[B_*T_*H_];
__device__ float g_k[B_*T_*H_];
__device__ float g_v[B_*T_*H_];

// 40 used (ta,tc) tiles of the 128x64 G band (ta=byte>>3, tc=byte&7)
__device__ __constant__ unsigned char G_TILES[40] = {
    6,7,
    12,13,14,15,
    18,19,20,21,22,23,
    24,25,26,27,28,29,30,31,
    32,33,34,35,36,37,38,39,
    40,41,42,43,44,45,
    48,49,50,51,
    56,57
};

// ---------------------------------------------------------------------------
// tf32 helpers
// ---------------------------------------------------------------------------
__device__ __forceinline__ uint32_t tf32_of(float x) {
    uint32_t u;
    asm("cvt.rna.tf32.f32 %0, %1;" : "=r"(u) : "f"(x));
    return u;
}
struct TF2 { uint32_t hi, lo; };
__device__ __forceinline__ TF2 tf32_split(float x) {
    TF2 r;
    r.hi = tf32_of(x);
    r.lo = tf32_of(x - __uint_as_float(r.hi));
    return r;
}
__device__ __forceinline__ float2 split_f2(float x) {
    TF2 t = tf32_split(x);
    return make_float2(__uint_as_float(t.hi), __uint_as_float(t.lo));
}
__device__ __forceinline__ void mma8(float* c,
    uint32_t a0, uint32_t a1, uint32_t a2, uint32_t a3,
    uint32_t b0, uint32_t b1)
{
    asm volatile(
        "mma.sync.aligned.m16n8k8.row.col.f32.tf32.tf32.f32 "
        "{%0,%1,%2,%3}, {%4,%5,%6,%7}, {%8,%9}, {%0,%1,%2,%3};"
        : "+f"(c[0]), "+f"(c[1]), "+f"(c[2]), "+f"(c[3])
        : "r"(a0), "r"(a1), "r"(a2), "r"(a3), "r"(b0), "r"(b1));
}

// acc[NB][4] += A(16 rows of sA @arow0, fp32, split in reg) x B^T
// B pre-split float2(hi,lo), rows are n (stride 68 float2), cols k.
template<int NB>
__device__ __forceinline__ void gemm_As_B2(
    const float* __restrict__ sA, int arow0,
    const float2* __restrict__ sB2, int n0, int lane, float (*acc)[4])
{
    const int gid = lane >> 2, tig = lane & 3;
    #pragma unroll
    for (int kk = 0; kk < 8; ++kk) {
        const int kb = kk * 8;
        TF2 a0 = tf32_split(sA[(arow0+gid  )*68 + kb + tig    ]);
        TF2 a1 = tf32_split(sA[(arow0+gid+8)*68 + kb + tig    ]);
        TF2 a2 = tf32_split(sA[(arow0+gid  )*68 + kb + tig + 4]);
        TF2 a3 = tf32_split(sA[(arow0+gid+8)*68 + kb + tig + 4]);
        #pragma unroll
        for (int n = 0; n < NB; ++n) {
            float2 b0 = sB2[((n0+n)*8+gid)*68 + kb + tig    ];
            float2 b1 = sB2[((n0+n)*8+gid)*68 + kb + tig + 4];
            uint32_t b0h = __float_as_uint(b0.x), b0l = __float_as_uint(b0.y);
            uint32_t b1h = __float_as_uint(b1.x), b1l = __float_as_uint(b1.y);
            mma8(acc[n], a0.hi, a1.hi, a2.hi, a3.hi, b0h, b1h);
            mma8(acc[n], a0.lo, a1.lo, a2.lo, a3.lo, b0h, b1h);
            mma8(acc[n], a0.hi, a1.hi, a2.hi, a3.hi, b0l, b1l);
        }
    }
}

// One 16x8 G tile: acc[4] += E(16 rows @arow0) x Qc^T(8 cols @tc*8)
__device__ __forceinline__ void gemm_G_tile(
    const float* __restrict__ sE, int arow0,
    const float2* __restrict__ sQc2, int tc, int lane, float* acc)
{
    const int gid = lane >> 2, tig = lane & 3;
    #pragma unroll
    for (int kk = 0; kk < 8; ++kk) {
        const int kb = kk * 8;
        TF2 a0 = tf32_split(sE[(arow0+gid  )*68 + kb + tig    ]);
        TF2 a1 = tf32_split(sE[(arow0+gid+8)*68 + kb + tig    ]);
        TF2 a2 = tf32_split(sE[(arow0+gid  )*68 + kb + tig + 4]);
        TF2 a3 = tf32_split(sE[(arow0+gid+8)*68 + kb + tig + 4]);
        float2 b0 = sQc2[(tc*8+gid)*68 + kb + tig    ];
        float2 b1 = sQc2[(tc*8+gid)*68 + kb + tig + 4];
        uint32_t b0h = __float_as_uint(b0.x), b0l = __float_as_uint(b0.y);
        uint32_t b1h = __float_as_uint(b1.x), b1l = __float_as_uint(b1.y);
        mma8(acc, a0.hi, a1.hi, a2.hi, a3.hi, b0h, b1h);
        mma8(acc, a0.lo, a1.lo, a2.lo, a3.lo, b0h, b1h);
        mma8(acc, a0.hi, a1.hi, a2.hi, a3.hi, b0l, b1l);
    }
}

// acc[2][4] += P x V, single tf32. sP stride 68 [r][s]; sVt stride 65 [h][s].
__device__ __forceinline__ void gemm_pv(
    const float* __restrict__ sPb, int arow0,
    const float* __restrict__ sVb, int n0, int lane, float (*acc)[4])
{
    const int gid = lane >> 2, tig = lane & 3;
    #pragma unroll
    for (int kk = 0; kk < 8; ++kk) {
        const int kb = kk * 8;
        uint32_t a0 = __float_as_uint(sPb[(arow0+gid  )*68 + kb + tig    ]);
        uint32_t a1 = __float_as_uint(sPb[(arow0+gid+8)*68 + kb + tig    ]);
        uint32_t a2 = __float_as_uint(sPb[(arow0+gid  )*68 + kb + tig + 4]);
        uint32_t a3 = __float_as_uint(sPb[(arow0+gid+8)*68 + kb + tig + 4]);
        #pragma unroll
        for (int n = 0; n < 2; ++n) {
            uint32_t b0 = __float_as_uint(sVb[((n0+n)*8+gid)*65 + kb + tig    ]);
            uint32_t b1 = __float_as_uint(sVb[((n0+n)*8+gid)*65 + kb + tig + 4]);
            mma8(acc[n], a0, a1, a2, a3, b0, b1);
        }
    }
}

// ---------------------------------------------------------------------------
// Kernel 1: QKV projection, one matrix per blockIdx.y. 256 thr, 128 rows/CTA.
// ---------------------------------------------------------------------------
#define PX_OFF 0
#define PW_OFF 8704
#define PSMEM_FLOATS 17408
#define PSMEM_BYTES (PSMEM_FLOATS*4)

__global__ __launch_bounds__(256) void proj_kernel(
    const float* __restrict__ x,
    const float* __restrict__ Wq,
    const float* __restrict__ Wk,
    const float* __restrict__ Wv)
{
    extern __shared__ float sm[];
    float*  sX  = sm + PX_OFF;
    float2* sW2 = (float2*)(sm + PW_OFF);

    const int tid  = threadIdx.x;
    const int w    = tid >> 5;
    const int lane = tid & 31;
    const int gid  = lane >> 2;
    const int tig  = lane & 3;
    const int row0 = blockIdx.x * 128;

    const float* __restrict__ W;
    float* __restrict__ outp;
    if (blockIdx.y == 0)      { W = Wq; outp = g_q; }
    else if (blockIdx.y == 1) { W = Wk; outp = g_k; }
    else                      { W = Wv; outp = g_v; }

    float acc[8][4];
    #pragma unroll
    for (int n = 0; n < 8; ++n)
        #pragma unroll
        for (int j = 0; j < 4; ++j) acc[n][j] = 0.f;

    for (int kc = 0; kc < C_; kc += 64) {
        __syncthreads();
        {
            int rr = tid >> 1, c0 = (tid & 1) * 32;
            const float4* xp = (const float4*)&x[(size_t)(row0 + rr) * C_ + kc + c0];
            #pragma unroll
            for (int u = 0; u < 8; ++u)
                *(float4*)&sX[rr*68 + c0 + u*4] = xp[u];
        }
        {
            int c = tid >> 2, h0 = (tid & 3) * 16;
            const float4* wp = (const float4*)&W[(size_t)(kc + c) * H_ + h0];
            #pragma unroll
            for (int u = 0; u < 4; ++u) {
                float4 wv = wp[u];
                int h = h0 + u*4;
                sW2[(h+0)*68 + c] = split_f2(wv.x);
                sW2[(h+1)*68 + c] = split_f2(wv.y);
                sW2[(h+2)*68 + c] = split_f2(wv.z);
                sW2[(h+3)*68 + c] = split_f2(wv.w);
            }
        }
        __syncthreads();
        gemm_As_B2<8>(sX, w*16, sW2, 0, lane, acc);
    }

    const int r = row0 + w*16 + gid;
    #pragma unroll
    for (int n = 0; n < 8; ++n) {
        int h0 = n*8 + 2*tig;
        *(float2*)&outp[(size_t)r*H_ + h0]     = make_float2(acc[n][0], acc[n][1]);
        *(float2*)&outp[(size_t)(r+8)*H_ + h0] = make_float2(acc[n][2], acc[n][3]);
    }
}

// ---------------------------------------------------------------------------
// Kernel 2: attention. 512 threads (16 warps: wr=w&3 rows, wg=w>>2 col quarter)
// R3-proven rel math: G[a][c] = Er[d-65+a].q[s0+1+c] (OOB -> 0);
//   S[r][c] += G[r-c+63][c]; diag: +q[t].Er[T-1]; mask c>r on last tile.
// G computed only on the 40 used 16x8 tiles (triangle skip).
// ---------------------------------------------------------------------------
#define AQ_OFF    0        /* 64x68 fp32                  */
#define AK2_OFF   4352     /* float2 64x68 (8704 fl)      */
#define AQC2_OFF  13056    /* float2 64x68 (8704 fl)      */
#define AVT_OFF   21760    /* 64x65 tf32 bits [h][s]      */
#define AG_OFF    25920    /* 128x68 fp32                 */
#define AE_OFF    34624    /* 128x68 fp32; sP aliases low */
#define ADIAG_OFF 43328    /* 64   */
#define AMAX_OFF  43392    /* 4x64 */
#define ASUM_OFF  43648    /* 4x64 */
#define ASMEM_FLOATS 43904
#define ASMEM_BYTES (ASMEM_FLOATS*4)

__global__ __launch_bounds__(512) void attn_kernel(
    const float* __restrict__ Er,
    float* __restrict__ out)
{
    extern __shared__ float sm[];
    float*  sQ    = sm + AQ_OFF;
    float2* sK2   = (float2*)(sm + AK2_OFF);
    float2* sQc2  = (float2*)(sm + AQC2_OFF);
    float*  sVt   = sm + AVT_OFF;
    float*  sG    = sm + AG_OFF;
    float*  sE    = sm + AE_OFF;
    float*  sP    = sm + AE_OFF;           // aliased (disjoint lifetime)
    float*  sDiag = sm + ADIAG_OFF;
    float*  sMax  = sm + AMAX_OFF;
    float*  sSum  = sm + ASUM_OFF;

    const int tid  = threadIdx.x;
    const int w    = tid >> 5;
    const int lane = tid & 31;
    const int gid  = lane >> 2;
    const int tig  = lane & 3;
    const int wr   = w & 3;
    const int wg   = w >> 2;
    const int m    = 31 - (int)blockIdx.x;     // big tiles first
    const int b    = blockIdx.y;
    const int t0   = m * 64;
    const size_t bT = (size_t)b * T_;
    const int r0   = wr*16 + gid;

    {   // Q tile
        int rr = tid >> 3, h0 = (tid & 7) * 8;
        const float4* qp = (const float4*)&g_q[(bT + t0 + rr)*H_ + h0];
        *(float4*)&sQ[rr*68 + h0]     = qp[0];
        *(float4*)&sQ[rr*68 + h0 + 4] = qp[1];
    }
    __syncthreads();

    if (tid < 256) {   // diag[r] = q[t0+r] . Er[T-1]
        int r = tid >> 2, qd = tid & 3;
        const float* er = Er + (size_t)(T_-1) * H_;
        float p = 0.f;
        #pragma unroll
        for (int hh = 0; hh < 16; ++hh) {
            int h = qd*16 + hh;
            p += sQ[r*68 + h] * er[h];
        }
        p += __shfl_xor_sync(0xffffffffu, p, 1);
        p += __shfl_xor_sync(0xffffffffu, p, 2);
        if (qd == 0) sDiag[r] = p;
    }

    float o[2][4];
    float mrow0 = -3.0e38f, mrow1 = -3.0e38f, lrow0 = 0.f, lrow1 = 0.f;
    #pragma unroll
    for (int n = 0; n < 2; ++n)
        #pragma unroll
        for (int j = 0; j < 4; ++j) o[n][j] = 0.f;

    for (int jt = 0; jt <= m; ++jt) {
        const int s0 = jt * 64;
        const int d  = t0 - s0;
        __syncthreads();   // (1) prev PV done; safe to overwrite tiles

        {   // K split, Qc split, V tf32 transposed (64 rows, 8 floats/thread)
            int rr = tid >> 3, h0 = (tid & 7) * 8;
            const float4* kp = (const float4*)&g_k[(bT + s0 + rr)*H_ + h0];
            float4 k0 = kp[0], k1 = kp[1];
            sK2[rr*68 + h0+0] = split_f2(k0.x);
            sK2[rr*68 + h0+1] = split_f2(k0.y);
            sK2[rr*68 + h0+2] = split_f2(k0.z);
            sK2[rr*68 + h0+3] = split_f2(k0.w);
            sK2[rr*68 + h0+4] = split_f2(k1.x);
            sK2[rr*68 + h0+5] = split_f2(k1.y);
            sK2[rr*68 + h0+6] = split_f2(k1.z);
            sK2[rr*68 + h0+7] = split_f2(k1.w);
            int qr = s0 + 1 + rr;
            float4 q0 = make_float4(0.f,0.f,0.f,0.f), q1 = q0;
            if (qr < T_) {
                const float4* qp = (const float4*)&g_q[(bT + qr)*H_ + h0];
                q0 = qp[0]; q1 = qp[1];
            }
            sQc2[rr*68 + h0+0] = split_f2(q0.x);
            sQc2[rr*68 + h0+1] = split_f2(q0.y);
            sQc2[rr*68 + h0+2] = split_f2(q0.z);
            sQc2[rr*68 + h0+3] = split_f2(q0.w);
            sQc2[rr*68 + h0+4] = split_f2(q1.x);
            sQc2[rr*68 + h0+5] = split_f2(q1.y);
            sQc2[rr*68 + h0+6] = split_f2(q1.z);
            sQc2[rr*68 + h0+7] = split_f2(q1.w);
            const float4* vp = (const float4*)&g_v[(bT + s0 + rr)*H_ + h0];
            float4 v0 = vp[0], v1 = vp[1];
            sVt[(h0+0)*65 + rr] = __uint_as_float(tf32_of(v0.x));
            sVt[(h0+1)*65 + rr] = __uint_as_float(tf32_of(v0.y));
            sVt[(h0+2)*65 + rr] = __uint_as_float(tf32_of(v0.z));
            sVt[(h0+3)*65 + rr] = __uint_as_float(tf32_of(v0.w));
            sVt[(h0+4)*65 + rr] = __uint_as_float(tf32_of(v1.x));
            sVt[(h0+5)*65 + rr] = __uint_as_float(tf32_of(v1.y));
            sVt[(h0+6)*65 + rr] = __uint_as_float(tf32_of(v1.z));
            sVt[(h0+7)*65 + rr] = __uint_as_float(tf32_of(v1.w));
        }
        {   // Er band 128 rows (16 floats/thread), OOB -> 0
            int rr = tid >> 2, h0 = (tid & 3) * 16;
            int e = d - 65 + rr;
            if (e >= 0) {
                const float4* ep = (const float4*)&Er[(size_t)e*H_ + h0];
                #pragma unroll
                for (int u = 0; u < 4; ++u)
                    *(float4*)&sE[rr*68 + h0 + u*4] = ep[u];
            } else {
                float4 z = make_float4(0.f,0.f,0.f,0.f);
                #pragma unroll
                for (int u = 0; u < 4; ++u)
                    *(float4*)&sE[rr*68 + h0 + u*4] = z;
            }
        }
        __syncthreads();   // (2)

        // G band tiles (flat-assigned from the 40-entry table)
        #pragma unroll
        for (int ti = 0; ti < 3; ++ti) {
            int idx = w + ti*16;
            if (idx < 40) {
                int tile = G_TILES[idx];
                int ta = tile >> 3, tc = tile & 7;
                float gacc[4] = {0.f, 0.f, 0.f, 0.f};
                gemm_G_tile(sE, ta*16, sQc2, tc, lane, gacc);
                int ar = ta*16 + gid, c0 = tc*8 + 2*tig;
                sG[ ar   *68 + c0    ] = gacc[0];
                sG[ ar   *68 + c0 + 1] = gacc[1];
                sG[(ar+8)*68 + c0    ] = gacc[2];
                sG[(ar+8)*68 + c0 + 1] = gacc[3];
            }
        }

        // S = Q x K^T (this warp's 16 rows x 16-col quarter)
        float s[2][4];
        #pragma unroll
        for (int n = 0; n < 2; ++n)
            #pragma unroll
            for (int j = 0; j < 4; ++j) s[n][j] = 0.f;
        gemm_As_B2<2>(sQ, wr*16, sK2, wg*2, lane, s);
        __syncthreads();   // (3) sG complete

        // gather + mask + local max
        const bool dt = (jt == m);
        float mt0 = -3.0e38f, mt1 = -3.0e38f;
        #pragma unroll
        for (int n = 0; n < 2; ++n) {
            #pragma unroll
            for (int j = 0; j < 4; ++j) {
                int c = (wg*2+n)*8 + 2*tig + (j & 1);
                int r = r0 + ((j >= 2) ? 8 : 0);
                float v = s[n][j] * 0.125f + sG[(r - c + 63)*68 + c];
                if (dt) {
                    if (c > r)       v = -3.0e38f;
                    else if (c == r) v += sDiag[r];
                }
                s[n][j] = v;
                if (j < 2) mt0 = fmaxf(mt0, v);
                else       mt1 = fmaxf(mt1, v);
            }
        }
        mt0 = fmaxf(mt0, __shfl_xor_sync(0xffffffffu, mt0, 1));
        mt0 = fmaxf(mt0, __shfl_xor_sync(0xffffffffu, mt0, 2));
        mt1 = fmaxf(mt1, __shfl_xor_sync(0xffffffffu, mt1, 1));
        mt1 = fmaxf(mt1, __shfl_xor_sync(0xffffffffu, mt1, 2));
        if (tig == 0) {
            sMax[wg*64 + r0]     = mt0;
            sMax[wg*64 + r0 + 8] = mt1;
        }
        __syncthreads();   // (4)

        float mn0 = mrow0, mn1 = mrow1;
        #pragma unroll
        for (int g = 0; g < 4; ++g) {
            mn0 = fmaxf(mn0, sMax[g*64 + r0]);
            mn1 = fmaxf(mn1, sMax[g*64 + r0 + 8]);
        }
        float cor0 = __expf(mrow0 - mn0);
        float cor1 = __expf(mrow1 - mn1);
        mrow0 = mn0; mrow1 = mn1;

        float sum0 = 0.f, sum1 = 0.f;
        #pragma unroll
        for (int n = 0; n < 2; ++n) {
            float p0 = __expf(s[n][0] - mn0);
            float p1 = __expf(s[n][1] - mn0);
            float p2 = __expf(s[n][2] - mn1);
            float p3 = __expf(s[n][3] - mn1);
            sum0 += p0 + p1; sum1 += p2 + p3;
            int c0 = (wg*2+n)*8 + 2*tig;
            *(float2*)&sP[ r0   *68 + c0] = make_float2(
                __uint_as_float(tf32_of(p0)), __uint_as_float(tf32_of(p1)));
            *(float2*)&sP[(r0+8)*68 + c0] = make_float2(
                __uint_as_float(tf32_of(p2)), __uint_as_float(tf32_of(p3)));
            o[n][0] *= cor0; o[n][1] *= cor0;
            o[n][2] *= cor1; o[n][3] *= cor1;
        }
        sum0 += __shfl_xor_sync(0xffffffffu, sum0, 1);
        sum0 += __shfl_xor_sync(0xffffffffu, sum0, 2);
        sum1 += __shfl_xor_sync(0xffffffffu, sum1, 1);
        sum1 += __shfl_xor_sync(0xffffffffu, sum1, 2);
        if (tig == 0) {
            sSum[wg*64 + r0]     = sum0;
            sSum[wg*64 + r0 + 8] = sum1;
        }
        __syncthreads();   // (5) sP + partials complete

        float ts0 = 0.f, ts1 = 0.f;
        #pragma unroll
        for (int g = 0; g < 4; ++g) {
            ts0 += sSum[g*64 + r0];
            ts1 += sSum[g*64 + r0 + 8];
        }
        lrow0 = lrow0 * cor0 + ts0;
        lrow1 = lrow1 * cor1 + ts1;

        gemm_pv(sP, wr*16, sVt, wg*2, lane, o);
    }

    float inv0 = 1.f / lrow0;
    float inv1 = 1.f / lrow1;
    #pragma unroll
    for (int n = 0; n < 2; ++n) {
        int c0 = (wg*2+n)*8 + 2*tig;
        *(float2*)&out[(bT + t0 + r0    )*H_ + c0] =
            make_float2(o[n][0]*inv0, o[n][1]*inv0);
        *(float2*)&out[(bT + t0 + r0 + 8)*H_ + c0] =
            make_float2(o[n][2]*inv1, o[n][3]*inv1);
    }
}

// ---------------------------------------------------------------------------
extern "C" void kernel_launch(void* const* d_in, const int* in_sizes, int n_in,
                              void* d_out, int out_size)
{
    const float* x  = (const float*)d_in[0];
    const float* Wq = (const float*)d_in[1];
    const float* Wk = (const float*)d_in[2];
    const float* Wv = (const float*)d_in[3];
    const float* Er = (const float*)d_in[4];
    float* out = (float*)d_out;

    cudaFuncSetAttribute(proj_kernel,
                         cudaFuncAttributeMaxDynamicSharedMemorySize, PSMEM_BYTES);
    cudaFuncSetAttribute(attn_kernel,
                         cudaFuncAttributeMaxDynamicSharedMemorySize, ASMEM_BYTES);

    proj_kernel<<<dim3(256, 3), 256, PSMEM_BYTES>>>(x, Wq, Wk, Wv);
    attn_kernel<<<dim3(32, 16), 512, ASMEM_BYTES>>>(Er, out);
}

// round 6
// speedup vs baseline: 1.7379x; 1.7379x over previous
#include <cuda_runtime.h>
#include <cuda_bf16.h>
#include <math.h>
#include <stdint.h>

#define B_ 16
#define T_ 2048
#define C_ 512
#define H_ 64
#define SW 36   /* smem plane row stride in 32-bit words (72 bf16) */

// Global scratch: bf16 hi/lo planes (allowed __device__ scratch path)
__device__ __nv_bfloat16 g_qhi[B_*T_*H_], g_qlo[B_*T_*H_];
__device__ __nv_bfloat16 g_khi[B_*T_*H_], g_klo[B_*T_*H_];
__device__ __nv_bfloat16 g_vthi[B_*H_*T_], g_vtlo[B_*H_*T_];   // [b][h][t]
__device__ __nv_bfloat16 g_erhi[T_*H_], g_erlo[T_*H_];

// 20 G band segments (16 rows x 16 cols each): (ta, c0-tile-pair)
__constant__ signed char GSEG_TA[20] = {0,1,1,2,2,2,3,3,3,3,4,4,4,4,5,5,5,6,6,7};
__constant__ signed char GSEG_C [20] = {6,4,6,2,4,6,0,2,4,6,0,2,4,6,0,2,4,0,2,0};

// ---------------------------------------------------------------------------
// helpers
// ---------------------------------------------------------------------------
__device__ __forceinline__ uint32_t tf32_of(float x) {
    uint32_t u; asm("cvt.rna.tf32.f32 %0, %1;" : "=r"(u) : "f"(x)); return u;
}
struct TF2 { uint32_t hi, lo; };
__device__ __forceinline__ TF2 tf32_split(float x) {
    TF2 r; r.hi = tf32_of(x);
    r.lo = tf32_of(x - __uint_as_float(r.hi)); return r;
}
__device__ __forceinline__ float2 split_f2(float x) {
    TF2 t = tf32_split(x);
    return make_float2(__uint_as_float(t.hi), __uint_as_float(t.lo));
}
__device__ __forceinline__ void bsplit(float x, __nv_bfloat16& h, __nv_bfloat16& l) {
    h = __float2bfloat16_rn(x);
    l = __float2bfloat16_rn(x - __bfloat162float(h));
}
__device__ __forceinline__ void mma8(float* c,
    uint32_t a0, uint32_t a1, uint32_t a2, uint32_t a3, uint32_t b0, uint32_t b1)
{
    asm volatile(
        "mma.sync.aligned.m16n8k8.row.col.f32.tf32.tf32.f32 "
        "{%0,%1,%2,%3}, {%4,%5,%6,%7}, {%8,%9}, {%0,%1,%2,%3};"
        : "+f"(c[0]), "+f"(c[1]), "+f"(c[2]), "+f"(c[3])
        : "r"(a0), "r"(a1), "r"(a2), "r"(a3), "r"(b0), "r"(b1));
}
__device__ __forceinline__ void mmabf(float* c,
    uint32_t a0, uint32_t a1, uint32_t a2, uint32_t a3, uint32_t b0, uint32_t b1)
{
    asm volatile(
        "mma.sync.aligned.m16n8k16.row.col.f32.bf16.bf16.f32 "
        "{%0,%1,%2,%3}, {%4,%5,%6,%7}, {%8,%9}, {%0,%1,%2,%3};"
        : "+f"(c[0]), "+f"(c[1]), "+f"(c[2]), "+f"(c[3])
        : "r"(a0), "r"(a1), "r"(a2), "r"(a3), "r"(b0), "r"(b1));
}

// acc[2][4] += A(16 rows @ar0, 2-plane bf16) x B^T(16 cols @n0*8, 2-plane)
// planes are uint32 arrays, row stride SW words (2 bf16 per word, k-pairs).
__device__ __forceinline__ void gemm16(
    const uint32_t* __restrict__ Ah, const uint32_t* __restrict__ Al, int ar0,
    const uint32_t* __restrict__ Bh, const uint32_t* __restrict__ Bl, int n0,
    int lane, float (*acc)[4])
{
    const int gid = lane >> 2, tig = lane & 3;
    #pragma unroll
    for (int ck = 0; ck < 4; ++ck) {
        const int kw = ck * 8;
        uint32_t a0h = Ah[(ar0+gid  )*SW + kw + tig];
        uint32_t a1h = Ah[(ar0+gid+8)*SW + kw + tig];
        uint32_t a2h = Ah[(ar0+gid  )*SW + kw + 4 + tig];
        uint32_t a3h = Ah[(ar0+gid+8)*SW + kw + 4 + tig];
        uint32_t a0l = Al[(ar0+gid  )*SW + kw + tig];
        uint32_t a1l = Al[(ar0+gid+8)*SW + kw + tig];
        uint32_t a2l = Al[(ar0+gid  )*SW + kw + 4 + tig];
        uint32_t a3l = Al[(ar0+gid+8)*SW + kw + 4 + tig];
        #pragma unroll
        for (int n = 0; n < 2; ++n) {
            int br = (n0+n)*8 + gid;
            uint32_t b0h = Bh[br*SW + kw + tig];
            uint32_t b1h = Bh[br*SW + kw + 4 + tig];
            uint32_t b0l = Bl[br*SW + kw + tig];
            uint32_t b1l = Bl[br*SW + kw + 4 + tig];
            mmabf(acc[n], a0h, a1h, a2h, a3h, b0h, b1h);
            mmabf(acc[n], a0l, a1l, a2l, a3l, b0h, b1h);
            mmabf(acc[n], a0h, a1h, a2h, a3h, b0l, b1l);
        }
    }
}

// tf32 proj gemm (unchanged, proven): acc[8][4] += A x B^T, B pre-split float2
__device__ __forceinline__ void gemm_As_B2_8(
    const float* __restrict__ sA, int arow0,
    const float2* __restrict__ sB2, int lane, float (*acc)[4])
{
    const int gid = lane >> 2, tig = lane & 3;
    #pragma unroll
    for (int kk = 0; kk < 8; ++kk) {
        const int kb = kk * 8;
        TF2 a0 = tf32_split(sA[(arow0+gid  )*68 + kb + tig    ]);
        TF2 a1 = tf32_split(sA[(arow0+gid+8)*68 + kb + tig    ]);
        TF2 a2 = tf32_split(sA[(arow0+gid  )*68 + kb + tig + 4]);
        TF2 a3 = tf32_split(sA[(arow0+gid+8)*68 + kb + tig + 4]);
        #pragma unroll
        for (int n = 0; n < 8; ++n) {
            float2 b0 = sB2[(n*8+gid)*68 + kb + tig    ];
            float2 b1 = sB2[(n*8+gid)*68 + kb + tig + 4];
            uint32_t b0h = __float_as_uint(b0.x), b0l = __float_as_uint(b0.y);
            uint32_t b1h = __float_as_uint(b1.x), b1l = __float_as_uint(b1.y);
            mma8(acc[n], a0.hi, a1.hi, a2.hi, a3.hi, b0h, b1h);
            mma8(acc[n], a0.lo, a1.lo, a2.lo, a3.lo, b0h, b1h);
            mma8(acc[n], a0.hi, a1.hi, a2.hi, a3.hi, b0l, b1l);
        }
    }
}

// ---------------------------------------------------------------------------
// Kernel 0: split Er into bf16 hi/lo planes
// ---------------------------------------------------------------------------
__global__ void er_prep(const float* __restrict__ Er)
{
    int i = blockIdx.x * blockDim.x + threadIdx.x;
    if (i < T_*H_) {
        __nv_bfloat16 h, l;
        bsplit(Er[i], h, l);
        g_erhi[i] = h; g_erlo[i] = l;
    }
}

// ---------------------------------------------------------------------------
// Kernel 1: QKV projection (tf32 3-split, proven) -> bf16 2-plane outputs.
// V written transposed [b][h][t].
// ---------------------------------------------------------------------------
#define PX_OFF 0
#define PW_OFF 8704
#define PSMEM_FLOATS 17408
#define PSMEM_BYTES (PSMEM_FLOATS*4)

__global__ __launch_bounds__(256) void proj_kernel(
    const float* __restrict__ x,
    const float* __restrict__ Wq,
    const float* __restrict__ Wk,
    const float* __restrict__ Wv)
{
    extern __shared__ float sm[];
    float*  sX  = sm + PX_OFF;
    float2* sW2 = (float2*)(sm + PW_OFF);

    const int tid  = threadIdx.x;
    const int w    = tid >> 5;
    const int lane = tid & 31;
    const int gid  = lane >> 2;
    const int tig  = lane & 3;
    const int row0 = blockIdx.x * 128;
    const int mat  = blockIdx.y;

    const float* __restrict__ W = (mat == 0) ? Wq : (mat == 1) ? Wk : Wv;

    float acc[8][4];
    #pragma unroll
    for (int n = 0; n < 8; ++n)
        #pragma unroll
        for (int j = 0; j < 4; ++j) acc[n][j] = 0.f;

    for (int kc = 0; kc < C_; kc += 64) {
        __syncthreads();
        {
            int rr = tid >> 1, c0 = (tid & 1) * 32;
            const float4* xp = (const float4*)&x[(size_t)(row0 + rr) * C_ + kc + c0];
            #pragma unroll
            for (int u = 0; u < 8; ++u)
                *(float4*)&sX[rr*68 + c0 + u*4] = xp[u];
        }
        {
            int c = tid >> 2, h0 = (tid & 3) * 16;
            const float4* wp = (const float4*)&W[(size_t)(kc + c) * H_ + h0];
            #pragma unroll
            for (int u = 0; u < 4; ++u) {
                float4 wv = wp[u];
                int h = h0 + u*4;
                sW2[(h+0)*68 + c] = split_f2(wv.x);
                sW2[(h+1)*68 + c] = split_f2(wv.y);
                sW2[(h+2)*68 + c] = split_f2(wv.z);
                sW2[(h+3)*68 + c] = split_f2(wv.w);
            }
        }
        __syncthreads();
        gemm_As_B2_8(sX, w*16, sW2, lane, acc);
    }

    const int r = row0 + w*16 + gid;        // global row (b*T + t)
    if (mat < 2) {
        __nv_bfloat16* ghi = (mat == 0) ? g_qhi : g_khi;
        __nv_bfloat16* glo = (mat == 0) ? g_qlo : g_klo;
        #pragma unroll
        for (int n = 0; n < 8; ++n) {
            int h0 = n*8 + 2*tig;
            __nv_bfloat16 h0b,l0b,h1b,l1b;
            bsplit(acc[n][0], h0b, l0b); bsplit(acc[n][1], h1b, l1b);
            __nv_bfloat162 th; th.x = h0b; th.y = h1b;
            __nv_bfloat162 tl; tl.x = l0b; tl.y = l1b;
            *(__nv_bfloat162*)&ghi[(size_t)r*H_ + h0] = th;
            *(__nv_bfloat162*)&glo[(size_t)r*H_ + h0] = tl;
            bsplit(acc[n][2], h0b, l0b); bsplit(acc[n][3], h1b, l1b);
            th.x = h0b; th.y = h1b; tl.x = l0b; tl.y = l1b;
            *(__nv_bfloat162*)&ghi[(size_t)(r+8)*H_ + h0] = th;
            *(__nv_bfloat162*)&glo[(size_t)(r+8)*H_ + h0] = tl;
        }
    } else {
        // V: transposed planes [b][h][t]
        #pragma unroll
        for (int n = 0; n < 8; ++n) {
            int h0 = n*8 + 2*tig;
            #pragma unroll
            for (int rr = 0; rr < 2; ++rr) {
                int rg = r + rr*8;
                int b  = rg >> 11, t = rg & 2047;
                float v0 = acc[n][rr*2], v1 = acc[n][rr*2+1];
                __nv_bfloat16 hb, lb;
                bsplit(v0, hb, lb);
                g_vthi[((size_t)b*H_ + h0    )*T_ + t] = hb;
                g_vtlo[((size_t)b*H_ + h0    )*T_ + t] = lb;
                bsplit(v1, hb, lb);
                g_vthi[((size_t)b*H_ + h0 + 1)*T_ + t] = hb;
                g_vtlo[((size_t)b*H_ + h0 + 1)*T_ + t] = lb;
            }
        }
    }
}

// ---------------------------------------------------------------------------
// Kernel 2: attention. 512 threads, 16 warps (wr=w&3 rows, wg=w>>2 col quarter)
// bf16 2-plane mma; softmax WITHOUT max subtraction (bounded logits);
// rel: G[a][c] = Er[d-65+a].q[s0+1+c] (OOB 0); S[r][c] += G[r-c+63][c];
// diag +q[t].Er[T-1], causal mask on last tile.
// ---------------------------------------------------------------------------
#define AQH   0
#define AQL   2304
#define AKH   4608
#define AKL   6912
#define AQCH  9216
#define AQCL  11520
#define AVH   13824
#define AVL   16128
#define AEH   18432   /* 128 x SW; sP hi aliases */
#define AEL   23040   /* 128 x SW; sP lo aliases */
#define AG    27648   /* 128 x 68 fp32 */
#define ADIAG 36352
#define ASUM  36416   /* 4 x 64 */
#define ASMEM_FLOATS 36672
#define ASMEM_BYTES (ASMEM_FLOATS*4)

__global__ __launch_bounds__(512) void attn_kernel(
    const float* __restrict__ Er,
    float* __restrict__ out)
{
    extern __shared__ float sm[];
    uint32_t* sQH  = (uint32_t*)(sm + AQH);
    uint32_t* sQL  = (uint32_t*)(sm + AQL);
    uint32_t* sKH  = (uint32_t*)(sm + AKH);
    uint32_t* sKL  = (uint32_t*)(sm + AKL);
    uint32_t* sQCH = (uint32_t*)(sm + AQCH);
    uint32_t* sQCL = (uint32_t*)(sm + AQCL);
    uint32_t* sVH  = (uint32_t*)(sm + AVH);
    uint32_t* sVL  = (uint32_t*)(sm + AVL);
    uint32_t* sEH  = (uint32_t*)(sm + AEH);
    uint32_t* sEL  = (uint32_t*)(sm + AEL);
    uint32_t* sPH  = sEH;                  // alias: disjoint lifetime
    uint32_t* sPL  = sEL;
    float*    sG   = sm + AG;
    float*    sDiag= sm + ADIAG;
    float*    sSum = sm + ASUM;

    const int tid  = threadIdx.x;
    const int w    = tid >> 5;
    const int lane = tid & 31;
    const int gid  = lane >> 2;
    const int tig  = lane & 3;
    const int wr   = w & 3;
    const int wg   = w >> 2;
    const int m    = 31 - (int)blockIdx.x;     // big tiles first
    const int b    = blockIdx.y;
    const int t0   = m * 64;
    const size_t bT = (size_t)b * T_;
    const int r0   = wr*16 + gid;

    const int frr = tid >> 3;           // 64-row fill index
    const int fh8 = tid & 7;            // 8 x 16B segments
    const int err_ = tid >> 2;          // 128-row fill index
    const int eq4 = tid & 3;            // 4 x 32B segments

    {   // prologue: Q planes
        *(uint4*)&sQH[frr*SW + fh8*4] =
            *(const uint4*)&g_qhi[(bT + t0 + frr)*H_ + fh8*8];
        *(uint4*)&sQL[frr*SW + fh8*4] =
            *(const uint4*)&g_qlo[(bT + t0 + frr)*H_ + fh8*8];
    }
    __syncthreads();

    if (tid < 256) {   // diag[r] = q[t0+r] . Er[T-1]
        int r = tid >> 2, qd = tid & 3;
        const float* er = Er + (size_t)(T_-1) * H_;
        const __nv_bfloat16* qh = (const __nv_bfloat16*)sQH;
        const __nv_bfloat16* ql = (const __nv_bfloat16*)sQL;
        float p = 0.f;
        #pragma unroll
        for (int hh = 0; hh < 16; ++hh) {
            int h = qd*16 + hh;
            float qv = __bfloat162float(qh[r*(2*SW) + h]) +
                       __bfloat162float(ql[r*(2*SW) + h]);
            p += qv * er[h];
        }
        p += __shfl_xor_sync(0xffffffffu, p, 1);
        p += __shfl_xor_sync(0xffffffffu, p, 2);
        if (qd == 0) sDiag[r] = p;
    }

    float o[2][4];
    float lr0 = 0.f, lr1 = 0.f;
    #pragma unroll
    for (int n = 0; n < 2; ++n)
        #pragma unroll
        for (int j = 0; j < 4; ++j) o[n][j] = 0.f;

    for (int jt = 0; jt <= m; ++jt) {
        const int s0 = jt * 64;
        const int d  = t0 - s0;
        __syncthreads();   // (1) prev PV done; tiles free

        {   // fill K, Qc, Vt, E planes (pure copies)
            *(uint4*)&sKH[frr*SW + fh8*4] =
                *(const uint4*)&g_khi[(bT + s0 + frr)*H_ + fh8*8];
            *(uint4*)&sKL[frr*SW + fh8*4] =
                *(const uint4*)&g_klo[(bT + s0 + frr)*H_ + fh8*8];
            int qr = s0 + 1 + frr;
            uint4 z = make_uint4(0u,0u,0u,0u);
            uint4 qh = z, ql = z;
            if (qr < T_) {
                qh = *(const uint4*)&g_qhi[(bT + qr)*H_ + fh8*8];
                ql = *(const uint4*)&g_qlo[(bT + qr)*H_ + fh8*8];
            }
            *(uint4*)&sQCH[frr*SW + fh8*4] = qh;
            *(uint4*)&sQCL[frr*SW + fh8*4] = ql;
            // V transposed planes: smem row = h, cols = s
            *(uint4*)&sVH[frr*SW + fh8*4] =
                *(const uint4*)&g_vthi[((size_t)b*H_ + frr)*T_ + s0 + fh8*8];
            *(uint4*)&sVL[frr*SW + fh8*4] =
                *(const uint4*)&g_vtlo[((size_t)b*H_ + frr)*T_ + s0 + fh8*8];
            // E band: 128 rows, OOB -> 0
            int e = d - 65 + err_;
            uint4 e0 = z, e1 = z, f0 = z, f1 = z;
            if (e >= 0) {
                const uint4* eh = (const uint4*)&g_erhi[(size_t)e*H_ + eq4*16];
                const uint4* el = (const uint4*)&g_erlo[(size_t)e*H_ + eq4*16];
                e0 = eh[0]; e1 = eh[1]; f0 = el[0]; f1 = el[1];
            }
            *(uint4*)&sEH[err_*SW + eq4*8    ] = e0;
            *(uint4*)&sEH[err_*SW + eq4*8 + 4] = e1;
            *(uint4*)&sEL[err_*SW + eq4*8    ] = f0;
            *(uint4*)&sEL[err_*SW + eq4*8 + 4] = f1;
        }
        __syncthreads();   // (2)

        // G segments (each warp: 1 or 2 segments of 16x16)
        for (int si = w; si < 20; si += 16) {
            int ta = GSEG_TA[si], c0t = GSEG_C[si];
            float g[2][4];
            #pragma unroll
            for (int n = 0; n < 2; ++n)
                #pragma unroll
                for (int j = 0; j < 4; ++j) g[n][j] = 0.f;
            gemm16(sEH, sEL, ta*16, sQCH, sQCL, c0t, lane, g);
            int ar = ta*16 + gid;
            #pragma unroll
            for (int n = 0; n < 2; ++n) {
                int cb = (c0t+n)*8 + 2*tig;
                *(float2*)&sG[ ar   *68 + cb] = make_float2(g[n][0], g[n][1]);
                *(float2*)&sG[(ar+8)*68 + cb] = make_float2(g[n][2], g[n][3]);
            }
        }

        // S = Q x K^T (16 rows x 16 cols per warp)
        float s[2][4];
        #pragma unroll
        for (int n = 0; n < 2; ++n)
            #pragma unroll
            for (int j = 0; j < 4; ++j) s[n][j] = 0.f;
        gemm16(sQH, sQL, wr*16, sKH, sKL, wg*2, lane, s);
        __syncthreads();   // (3) sG complete; sE reads done

        // gather + mask + exp + P store (2-plane bf16)
        const bool dt = (jt == m);
        __nv_bfloat16* pH = (__nv_bfloat16*)sPH;
        __nv_bfloat16* pL = (__nv_bfloat16*)sPL;
        #pragma unroll
        for (int n = 0; n < 2; ++n) {
            float p[4];
            #pragma unroll
            for (int j = 0; j < 4; ++j) {
                int c = (wg*2+n)*8 + 2*tig + (j & 1);
                int r = r0 + ((j >= 2) ? 8 : 0);
                float v = s[n][j] * 0.125f + sG[(r - c + 63)*68 + c];
                if (dt) {
                    if (c > r)       v = -3.0e38f;
                    else if (c == r) v += sDiag[r];
                }
                p[j] = __expf(v);
            }
            lr0 += p[0] + p[1];
            lr1 += p[2] + p[3];
            int c0 = (wg*2+n)*8 + 2*tig;
            __nv_bfloat16 h0b,l0b,h1b,l1b;
            bsplit(p[0], h0b, l0b); bsplit(p[1], h1b, l1b);
            __nv_bfloat162 th; th.x = h0b; th.y = h1b;
            __nv_bfloat162 tl; tl.x = l0b; tl.y = l1b;
            *(__nv_bfloat162*)&pH[r0*(2*SW) + c0] = th;
            *(__nv_bfloat162*)&pL[r0*(2*SW) + c0] = tl;
            bsplit(p[2], h0b, l0b); bsplit(p[3], h1b, l1b);
            th.x = h0b; th.y = h1b; tl.x = l0b; tl.y = l1b;
            *(__nv_bfloat162*)&pH[(r0+8)*(2*SW) + c0] = th;
            *(__nv_bfloat162*)&pL[(r0+8)*(2*SW) + c0] = tl;
        }
        __syncthreads();   // (4) sP complete

        // O += P x V^T  (2-plane x 2-plane, 3-product)
        gemm16(sPH, sPL, wr*16, sVH, sVL, wg*2, lane, o);
    }

    // final denominator reduce (once)
    lr0 += __shfl_xor_sync(0xffffffffu, lr0, 1);
    lr0 += __shfl_xor_sync(0xffffffffu, lr0, 2);
    lr1 += __shfl_xor_sync(0xffffffffu, lr1, 1);
    lr1 += __shfl_xor_sync(0xffffffffu, lr1, 2);
    if (tig == 0) {
        sSum[wg*64 + r0]     = lr0;
        sSum[wg*64 + r0 + 8] = lr1;
    }
    __syncthreads();
    float tl0 = 0.f, tl1 = 0.f;
    #pragma unroll
    for (int g = 0; g < 4; ++g) {
        tl0 += sSum[g*64 + r0];
        tl1 += sSum[g*64 + r0 + 8];
    }
    float inv0 = 1.f / tl0;
    float inv1 = 1.f / tl1;
    #pragma unroll
    for (int n = 0; n < 2; ++n) {
        int c0 = (wg*2+n)*8 + 2*tig;
        *(float2*)&out[(bT + t0 + r0    )*H_ + c0] =
            make_float2(o[n][0]*inv0, o[n][1]*inv0);
        *(float2*)&out[(bT + t0 + r0 + 8)*H_ + c0] =
            make_float2(o[n][2]*inv1, o[n][3]*inv1);
    }
}

// ---------------------------------------------------------------------------
extern "C" void kernel_launch(void* const* d_in, const int* in_sizes, int n_in,
                              void* d_out, int out_size)
{
    const float* x  = (const float*)d_in[0];
    const float* Wq = (const float*)d_in[1];
    const float* Wk = (const float*)d_in[2];
    const float* Wv = (const float*)d_in[3];
    const float* Er = (const float*)d_in[4];
    float* out = (float*)d_out;

    cudaFuncSetAttribute(proj_kernel,
                         cudaFuncAttributeMaxDynamicSharedMemorySize, PSMEM_BYTES);
    cudaFuncSetAttribute(attn_kernel,
                         cudaFuncAttributeMaxDynamicSharedMemorySize, ASMEM_BYTES);

    er_prep<<<(T_*H_ + 255)/256, 256>>>(Er);
    proj_kernel<<<dim3(256, 3), 256, PSMEM_BYTES>>>(x, Wq, Wk, Wv);
    attn_kernel<<<dim3(32, 16), 512, ASMEM_BYTES>>>(Er, out);
}

// round 7
// speedup vs baseline: 2.0763x; 1.1947x over previous
#include <cuda_runtime.h>
#include <cuda_bf16.h>
#include <math.h>
#include <stdint.h>

#define B_ 16
#define T_ 2048
#define C_ 512
#define H_ 64
#define SW 36   /* smem plane row stride in 32-bit words (72 bf16, 144 B) */

// Global scratch: bf16 hi/lo planes (allowed __device__ scratch path)
__device__ __nv_bfloat16 g_qhi[B_*T_*H_], g_qlo[B_*T_*H_];
__device__ __nv_bfloat16 g_khi[B_*T_*H_], g_klo[B_*T_*H_];
__device__ __nv_bfloat16 g_vthi[B_*H_*T_], g_vtlo[B_*H_*T_];   // [b][h][t]
__device__ __nv_bfloat16 g_erhi[T_*H_], g_erlo[T_*H_];

// 20 G band segments (16 rows x 16 cols each): (ta, c0-tile-pair)
__constant__ signed char GSEG_TA[20] = {0,1,1,2,2,2,3,3,3,3,4,4,4,4,5,5,5,6,6,7};
__constant__ signed char GSEG_C [20] = {6,4,6,2,4,6,0,2,4,6,0,2,4,6,0,2,4,0,2,0};

// ---------------------------------------------------------------------------
// helpers
// ---------------------------------------------------------------------------
__device__ __forceinline__ void bsplit(float x, __nv_bfloat16& h, __nv_bfloat16& l) {
    h = __float2bfloat16_rn(x);
    l = __float2bfloat16_rn(x - __bfloat162float(h));
}
__device__ __forceinline__ uint32_t smem_u32(const void* p) {
    return (uint32_t)__cvta_generic_to_shared(p);
}
__device__ __forceinline__ void ldsm_x4(uint32_t addr,
    uint32_t& r0, uint32_t& r1, uint32_t& r2, uint32_t& r3)
{
    asm volatile("ldmatrix.sync.aligned.m8n8.x4.shared.b16 {%0,%1,%2,%3}, [%4];"
        : "=r"(r0), "=r"(r1), "=r"(r2), "=r"(r3) : "r"(addr));
}
__device__ __forceinline__ void mmabf(float* c,
    uint32_t a0, uint32_t a1, uint32_t a2, uint32_t a3, uint32_t b0, uint32_t b1)
{
    asm volatile(
        "mma.sync.aligned.m16n8k16.row.col.f32.bf16.bf16.f32 "
        "{%0,%1,%2,%3}, {%4,%5,%6,%7}, {%8,%9}, {%0,%1,%2,%3};"
        : "+f"(c[0]), "+f"(c[1]), "+f"(c[2]), "+f"(c[3])
        : "r"(a0), "r"(a1), "r"(a2), "r"(a3), "r"(b0), "r"(b1));
}

// acc[2][4] += A(16 rows @ar0, 2-plane bf16) x B^T(16 cols @n0*8, 2-plane)
// All fragment loads via ldmatrix.x4 (stride 144B -> conflict-free).
__device__ __forceinline__ void gemm16(
    const uint32_t* __restrict__ Ah, const uint32_t* __restrict__ Al, int ar0,
    const uint32_t* __restrict__ Bh, const uint32_t* __restrict__ Bl, int n0,
    int lane, float (*acc)[4])
{
    const int la = lane & 7, l8 = (lane >> 3) & 1, l16 = lane >> 4;
    uint32_t aAh = smem_u32(Ah + (ar0 + la + l8*8)*SW) + l16*16;
    uint32_t aAl = smem_u32(Al + (ar0 + la + l8*8)*SW) + l16*16;
    uint32_t aBh = smem_u32(Bh + ((n0 + l16)*8 + la)*SW) + l8*16;
    uint32_t aBl = smem_u32(Bl + ((n0 + l16)*8 + la)*SW) + l8*16;
    #pragma unroll
    for (int ck = 0; ck < 4; ++ck) {
        uint32_t a0h,a1h,a2h,a3h, a0l,a1l,a2l,a3l;
        uint32_t p0h,p1h,q0h,q1h, p0l,p1l,q0l,q1l;
        ldsm_x4(aAh + ck*32, a0h,a1h,a2h,a3h);
        ldsm_x4(aAl + ck*32, a0l,a1l,a2l,a3l);
        ldsm_x4(aBh + ck*32, p0h,p1h,q0h,q1h);
        ldsm_x4(aBl + ck*32, p0l,p1l,q0l,q1l);
        mmabf(acc[0], a0h,a1h,a2h,a3h, p0h,p1h);
        mmabf(acc[0], a0l,a1l,a2l,a3l, p0h,p1h);
        mmabf(acc[0], a0h,a1h,a2h,a3h, p0l,p1l);
        mmabf(acc[1], a0h,a1h,a2h,a3h, q0h,q1h);
        mmabf(acc[1], a0l,a1l,a2l,a3l, q0h,q1h);
        mmabf(acc[1], a0h,a1h,a2h,a3h, q0l,q1l);
    }
}

// Proj version: acc[8][4] += A(16 rows) x B^T(64 cols). A loaded once per ck.
__device__ __forceinline__ void gemm16_n8(
    const uint32_t* __restrict__ Ah, const uint32_t* __restrict__ Al, int ar0,
    const uint32_t* __restrict__ Bh, const uint32_t* __restrict__ Bl,
    int lane, float (*acc)[4])
{
    const int la = lane & 7, l8 = (lane >> 3) & 1, l16 = lane >> 4;
    uint32_t aAh = smem_u32(Ah + (ar0 + la + l8*8)*SW) + l16*16;
    uint32_t aAl = smem_u32(Al + (ar0 + la + l8*8)*SW) + l16*16;
    uint32_t aBh = smem_u32(Bh + ((l16)*8 + la)*SW) + l8*16;
    uint32_t aBl = smem_u32(Bl + ((l16)*8 + la)*SW) + l8*16;
    #pragma unroll
    for (int ck = 0; ck < 4; ++ck) {
        uint32_t a0h,a1h,a2h,a3h, a0l,a1l,a2l,a3l;
        ldsm_x4(aAh + ck*32, a0h,a1h,a2h,a3h);
        ldsm_x4(aAl + ck*32, a0l,a1l,a2l,a3l);
        #pragma unroll
        for (int p = 0; p < 4; ++p) {
            uint32_t p0h,p1h,q0h,q1h, p0l,p1l,q0l,q1l;
            ldsm_x4(aBh + p*2304 + ck*32, p0h,p1h,q0h,q1h);
            ldsm_x4(aBl + p*2304 + ck*32, p0l,p1l,q0l,q1l);
            mmabf(acc[2*p  ], a0h,a1h,a2h,a3h, p0h,p1h);
            mmabf(acc[2*p  ], a0l,a1l,a2l,a3l, p0h,p1h);
            mmabf(acc[2*p  ], a0h,a1h,a2h,a3h, p0l,p1l);
            mmabf(acc[2*p+1], a0h,a1h,a2h,a3h, q0h,q1h);
            mmabf(acc[2*p+1], a0l,a1l,a2l,a3l, q0h,q1h);
            mmabf(acc[2*p+1], a0h,a1h,a2h,a3h, q0l,q1l);
        }
    }
}

// ---------------------------------------------------------------------------
// Kernel 0: split Er into bf16 hi/lo planes
// ---------------------------------------------------------------------------
__global__ void er_prep(const float* __restrict__ Er)
{
    int i = blockIdx.x * blockDim.x + threadIdx.x;
    if (i < T_*H_) {
        __nv_bfloat16 h, l;
        bsplit(Er[i], h, l);
        g_erhi[i] = h; g_erlo[i] = l;
    }
}

// ---------------------------------------------------------------------------
// Kernel 1: QKV projection, bf16 2-plane mma + ldmatrix.
// grid (256, 3): 128 rows/CTA, one W matrix per blockIdx.y; 256 thr (8 warps).
// ---------------------------------------------------------------------------
#define PXH 0
#define PXL 4608
#define PWH 9216
#define PWL 11520
#define PSMEM_FLOATS 13824
#define PSMEM_BYTES (PSMEM_FLOATS*4)

__global__ __launch_bounds__(256) void proj_kernel(
    const float* __restrict__ x,
    const float* __restrict__ Wq,
    const float* __restrict__ Wk,
    const float* __restrict__ Wv)
{
    extern __shared__ float sm[];
    uint32_t* sXH = (uint32_t*)(sm + PXH);
    uint32_t* sXL = (uint32_t*)(sm + PXL);
    uint32_t* sWH = (uint32_t*)(sm + PWH);
    uint32_t* sWL = (uint32_t*)(sm + PWL);

    const int tid  = threadIdx.x;
    const int w    = tid >> 5;
    const int lane = tid & 31;
    const int gid  = lane >> 2;
    const int tig  = lane & 3;
    const int row0 = blockIdx.x * 128;
    const int mat  = blockIdx.y;
    const float* __restrict__ W = (mat == 0) ? Wq : (mat == 1) ? Wk : Wv;

    float acc[8][4];
    #pragma unroll
    for (int n = 0; n < 8; ++n)
        #pragma unroll
        for (int j = 0; j < 4; ++j) acc[n][j] = 0.f;

    for (int kc = 0; kc < C_; kc += 64) {
        __syncthreads();
        {   // x tile 128x64 -> 2 bf16 planes
            int rr = tid >> 1, c0 = (tid & 1) * 32;
            const float4* xp = (const float4*)&x[(size_t)(row0 + rr) * C_ + kc + c0];
            __nv_bfloat162* dh = (__nv_bfloat162*)&sXH[rr*SW + c0/2];
            __nv_bfloat162* dl = (__nv_bfloat162*)&sXL[rr*SW + c0/2];
            #pragma unroll
            for (int u = 0; u < 8; ++u) {
                float4 v = xp[u];
                __nv_bfloat16 h0,l0,h1,l1;
                bsplit(v.x, h0, l0); bsplit(v.y, h1, l1);
                __nv_bfloat162 th; th.x = h0; th.y = h1;
                __nv_bfloat162 tl; tl.x = l0; tl.y = l1;
                dh[u*2]   = th; dl[u*2]   = tl;
                bsplit(v.z, h0, l0); bsplit(v.w, h1, l1);
                th.x = h0; th.y = h1; tl.x = l0; tl.y = l1;
                dh[u*2+1] = th; dl[u*2+1] = tl;
            }
        }
        {   // W chunk transpose+split: [h][k=c] planes
            int c = tid >> 2, h0 = (tid & 3) * 16;
            __nv_bfloat16* wh = (__nv_bfloat16*)sWH;
            __nv_bfloat16* wl = (__nv_bfloat16*)sWL;
            const float4* wp = (const float4*)&W[(size_t)(kc + c) * H_ + h0];
            #pragma unroll
            for (int u = 0; u < 4; ++u) {
                float4 v = wp[u];
                int h = h0 + u*4;
                __nv_bfloat16 hb, lb;
                bsplit(v.x, hb, lb); wh[(h+0)*(2*SW) + c] = hb; wl[(h+0)*(2*SW) + c] = lb;
                bsplit(v.y, hb, lb); wh[(h+1)*(2*SW) + c] = hb; wl[(h+1)*(2*SW) + c] = lb;
                bsplit(v.z, hb, lb); wh[(h+2)*(2*SW) + c] = hb; wl[(h+2)*(2*SW) + c] = lb;
                bsplit(v.w, hb, lb); wh[(h+3)*(2*SW) + c] = hb; wl[(h+3)*(2*SW) + c] = lb;
            }
        }
        __syncthreads();
        gemm16_n8(sXH, sXL, w*16, sWH, sWL, lane, acc);
    }

    const int r = row0 + w*16 + gid;        // global row (b*T + t)
    if (mat < 2) {
        __nv_bfloat16* ghi = (mat == 0) ? g_qhi : g_khi;
        __nv_bfloat16* glo = (mat == 0) ? g_qlo : g_klo;
        #pragma unroll
        for (int n = 0; n < 8; ++n) {
            int h0 = n*8 + 2*tig;
            __nv_bfloat16 h0b,l0b,h1b,l1b;
            bsplit(acc[n][0], h0b, l0b); bsplit(acc[n][1], h1b, l1b);
            __nv_bfloat162 th; th.x = h0b; th.y = h1b;
            __nv_bfloat162 tl; tl.x = l0b; tl.y = l1b;
            *(__nv_bfloat162*)&ghi[(size_t)r*H_ + h0] = th;
            *(__nv_bfloat162*)&glo[(size_t)r*H_ + h0] = tl;
            bsplit(acc[n][2], h0b, l0b); bsplit(acc[n][3], h1b, l1b);
            th.x = h0b; th.y = h1b; tl.x = l0b; tl.y = l1b;
            *(__nv_bfloat162*)&ghi[(size_t)(r+8)*H_ + h0] = th;
            *(__nv_bfloat162*)&glo[(size_t)(r+8)*H_ + h0] = tl;
        }
    } else {
        #pragma unroll
        for (int n = 0; n < 8; ++n) {
            int h0 = n*8 + 2*tig;
            #pragma unroll
            for (int rr = 0; rr < 2; ++rr) {
                int rg = r + rr*8;
                int b  = rg >> 11, t = rg & 2047;
                float v0 = acc[n][rr*2], v1 = acc[n][rr*2+1];
                __nv_bfloat16 hb, lb;
                bsplit(v0, hb, lb);
                g_vthi[((size_t)b*H_ + h0    )*T_ + t] = hb;
                g_vtlo[((size_t)b*H_ + h0    )*T_ + t] = lb;
                bsplit(v1, hb, lb);
                g_vthi[((size_t)b*H_ + h0 + 1)*T_ + t] = hb;
                g_vtlo[((size_t)b*H_ + h0 + 1)*T_ + t] = lb;
            }
        }
    }
}

// ---------------------------------------------------------------------------
// Kernel 2: attention. Same math as R6 (proven), now ldmatrix + gmem prefetch.
// 512 threads, 16 warps (wr=w&3 rows, wg=w>>2 col quarter).
// ---------------------------------------------------------------------------
#define AQH   0
#define AQL   2304
#define AKH   4608
#define AKL   6912
#define AQCH  9216
#define AQCL  11520
#define AVH   13824
#define AVL   16128
#define AEH   18432   /* 128 x SW; sP hi aliases */
#define AEL   23040   /* 128 x SW; sP lo aliases */
#define AG    27648   /* 128 x 68 fp32 */
#define ADIAG 36352
#define ASUM  36416   /* 4 x 64 */
#define ASMEM_FLOATS 36672
#define ASMEM_BYTES (ASMEM_FLOATS*4)

__global__ __launch_bounds__(512) void attn_kernel(
    const float* __restrict__ Er,
    float* __restrict__ out)
{
    extern __shared__ float sm[];
    uint32_t* sQH  = (uint32_t*)(sm + AQH);
    uint32_t* sQL  = (uint32_t*)(sm + AQL);
    uint32_t* sKH  = (uint32_t*)(sm + AKH);
    uint32_t* sKL  = (uint32_t*)(sm + AKL);
    uint32_t* sQCH = (uint32_t*)(sm + AQCH);
    uint32_t* sQCL = (uint32_t*)(sm + AQCL);
    uint32_t* sVH  = (uint32_t*)(sm + AVH);
    uint32_t* sVL  = (uint32_t*)(sm + AVL);
    uint32_t* sEH  = (uint32_t*)(sm + AEH);
    uint32_t* sEL  = (uint32_t*)(sm + AEL);
    uint32_t* sPH  = sEH;                  // alias: disjoint lifetime
    uint32_t* sPL  = sEL;
    float*    sG   = sm + AG;
    float*    sDiag= sm + ADIAG;
    float*    sSum = sm + ASUM;

    const int tid  = threadIdx.x;
    const int w    = tid >> 5;
    const int lane = tid & 31;
    const int gid  = lane >> 2;
    const int tig  = lane & 3;
    const int wr   = w & 3;
    const int wg   = w >> 2;
    const int m    = 31 - (int)blockIdx.x;     // big tiles first
    const int b    = blockIdx.y;
    const int t0   = m * 64;
    const size_t bT = (size_t)b * T_;
    const int r0   = wr*16 + gid;

    const int frr = tid >> 3;           // 64-row fill index
    const int fh8 = tid & 7;            // 8 x 16B segments
    const int err_ = tid >> 2;          // 128-row fill index
    const int eq4 = tid & 3;            // 4 x 32B segments

    {   // prologue: Q planes
        *(uint4*)&sQH[frr*SW + fh8*4] =
            *(const uint4*)&g_qhi[(bT + t0 + frr)*H_ + fh8*8];
        *(uint4*)&sQL[frr*SW + fh8*4] =
            *(const uint4*)&g_qlo[(bT + t0 + frr)*H_ + fh8*8];
    }
    __syncthreads();

    if (tid < 256) {   // diag[r] = q[t0+r] . Er[T-1]
        int r = tid >> 2, qd = tid & 3;
        const float* er = Er + (size_t)(T_-1) * H_;
        const __nv_bfloat16* qh = (const __nv_bfloat16*)sQH;
        const __nv_bfloat16* ql = (const __nv_bfloat16*)sQL;
        float p = 0.f;
        #pragma unroll
        for (int hh = 0; hh < 16; ++hh) {
            int h = qd*16 + hh;
            float qv = __bfloat162float(qh[r*(2*SW) + h]) +
                       __bfloat162float(ql[r*(2*SW) + h]);
            p += qv * er[h];
        }
        p += __shfl_xor_sync(0xffffffffu, p, 1);
        p += __shfl_xor_sync(0xffffffffu, p, 2);
        if (qd == 0) sDiag[r] = p;
    }

    float o[2][4];
    float lr0 = 0.f, lr1 = 0.f;
    #pragma unroll
    for (int n = 0; n < 2; ++n)
        #pragma unroll
        for (int j = 0; j < 4; ++j) o[n][j] = 0.f;

    for (int jt = 0; jt <= m; ++jt) {
        const int s0 = jt * 64;
        const int d  = t0 - s0;

        // prefetch gmem -> regs (overlaps the barrier wait)
        uint4 z = make_uint4(0u,0u,0u,0u);
        uint4 pkh = *(const uint4*)&g_khi[(bT + s0 + frr)*H_ + fh8*8];
        uint4 pkl = *(const uint4*)&g_klo[(bT + s0 + frr)*H_ + fh8*8];
        uint4 pvh = *(const uint4*)&g_vthi[((size_t)b*H_ + frr)*T_ + s0 + fh8*8];
        uint4 pvl = *(const uint4*)&g_vtlo[((size_t)b*H_ + frr)*T_ + s0 + fh8*8];
        int qr = s0 + 1 + frr;
        uint4 pqh = z, pql = z;
        if (qr < T_) {
            pqh = *(const uint4*)&g_qhi[(bT + qr)*H_ + fh8*8];
            pql = *(const uint4*)&g_qlo[(bT + qr)*H_ + fh8*8];
        }
        int e = d - 65 + err_;
        uint4 pe0 = z, pe1 = z, pf0 = z, pf1 = z;
        if (e >= 0) {
            const uint4* eh = (const uint4*)&g_erhi[(size_t)e*H_ + eq4*16];
            const uint4* el = (const uint4*)&g_erlo[(size_t)e*H_ + eq4*16];
            pe0 = eh[0]; pe1 = eh[1]; pf0 = el[0]; pf1 = el[1];
        }

        __syncthreads();   // (1) prev PV done; tiles free

        *(uint4*)&sKH[frr*SW + fh8*4] = pkh;
        *(uint4*)&sKL[frr*SW + fh8*4] = pkl;
        *(uint4*)&sQCH[frr*SW + fh8*4] = pqh;
        *(uint4*)&sQCL[frr*SW + fh8*4] = pql;
        *(uint4*)&sVH[frr*SW + fh8*4] = pvh;
        *(uint4*)&sVL[frr*SW + fh8*4] = pvl;
        *(uint4*)&sEH[err_*SW + eq4*8    ] = pe0;
        *(uint4*)&sEH[err_*SW + eq4*8 + 4] = pe1;
        *(uint4*)&sEL[err_*SW + eq4*8    ] = pf0;
        *(uint4*)&sEL[err_*SW + eq4*8 + 4] = pf1;
        __syncthreads();   // (2)

        // G segments (each warp: 1 or 2 segments of 16x16)
        for (int si = w; si < 20; si += 16) {
            int ta = GSEG_TA[si], c0t = GSEG_C[si];
            float g[2][4];
            #pragma unroll
            for (int n = 0; n < 2; ++n)
                #pragma unroll
                for (int j = 0; j < 4; ++j) g[n][j] = 0.f;
            gemm16(sEH, sEL, ta*16, sQCH, sQCL, c0t, lane, g);
            int ar = ta*16 + gid;
            #pragma unroll
            for (int n = 0; n < 2; ++n) {
                int cb = (c0t+n)*8 + 2*tig;
                *(float2*)&sG[ ar   *68 + cb] = make_float2(g[n][0], g[n][1]);
                *(float2*)&sG[(ar+8)*68 + cb] = make_float2(g[n][2], g[n][3]);
            }
        }

        // S = Q x K^T (16 rows x 16 cols per warp)
        float s[2][4];
        #pragma unroll
        for (int n = 0; n < 2; ++n)
            #pragma unroll
            for (int j = 0; j < 4; ++j) s[n][j] = 0.f;
        gemm16(sQH, sQL, wr*16, sKH, sKL, wg*2, lane, s);
        __syncthreads();   // (3) sG complete; sE reads done

        // gather + mask + exp + P store (2-plane bf16)
        const bool dt = (jt == m);
        __nv_bfloat16* pH = (__nv_bfloat16*)sPH;
        __nv_bfloat16* pL = (__nv_bfloat16*)sPL;
        #pragma unroll
        for (int n = 0; n < 2; ++n) {
            float p[4];
            #pragma unroll
            for (int j = 0; j < 4; ++j) {
                int c = (wg*2+n)*8 + 2*tig + (j & 1);
                int r = r0 + ((j >= 2) ? 8 : 0);
                float v = s[n][j] * 0.125f + sG[(r - c + 63)*68 + c];
                if (dt) {
                    if (c > r)       v = -3.0e38f;
                    else if (c == r) v += sDiag[r];
                }
                p[j] = __expf(v);
            }
            lr0 += p[0] + p[1];
            lr1 += p[2] + p[3];
            int c0 = (wg*2+n)*8 + 2*tig;
            __nv_bfloat16 h0b,l0b,h1b,l1b;
            bsplit(p[0], h0b, l0b); bsplit(p[1], h1b, l1b);
            __nv_bfloat162 th; th.x = h0b; th.y = h1b;
            __nv_bfloat162 tl; tl.x = l0b; tl.y = l1b;
            *(__nv_bfloat162*)&pH[r0*(2*SW) + c0] = th;
            *(__nv_bfloat162*)&pL[r0*(2*SW) + c0] = tl;
            bsplit(p[2], h0b, l0b); bsplit(p[3], h1b, l1b);
            th.x = h0b; th.y = h1b; tl.x = l0b; tl.y = l1b;
            *(__nv_bfloat162*)&pH[(r0+8)*(2*SW) + c0] = th;
            *(__nv_bfloat162*)&pL[(r0+8)*(2*SW) + c0] = tl;
        }
        __syncthreads();   // (4) sP complete

        // O += P x V^T  (2-plane x 2-plane, 3-product)
        gemm16(sPH, sPL, wr*16, sVH, sVL, wg*2, lane, o);
    }

    // final denominator reduce (once)
    lr0 += __shfl_xor_sync(0xffffffffu, lr0, 1);
    lr0 += __shfl_xor_sync(0xffffffffu, lr0, 2);
    lr1 += __shfl_xor_sync(0xffffffffu, lr1, 1);
    lr1 += __shfl_xor_sync(0xffffffffu, lr1, 2);
    if (tig == 0) {
        sSum[wg*64 + r0]     = lr0;
        sSum[wg*64 + r0 + 8] = lr1;
    }
    __syncthreads();
    float tl0 = 0.f, tl1 = 0.f;
    #pragma unroll
    for (int g = 0; g < 4; ++g) {
        tl0 += sSum[g*64 + r0];
        tl1 += sSum[g*64 + r0 + 8];
    }
    float inv0 = 1.f / tl0;
    float inv1 = 1.f / tl1;
    #pragma unroll
    for (int n = 0; n < 2; ++n) {
        int c0 = (wg*2+n)*8 + 2*tig;
        *(float2*)&out[(bT + t0 + r0    )*H_ + c0] =
            make_float2(o[n][0]*inv0, o[n][1]*inv0);
        *(float2*)&out[(bT + t0 + r0 + 8)*H_ + c0] =
            make_float2(o[n][2]*inv1, o[n][3]*inv1);
    }
}

// ---------------------------------------------------------------------------
extern "C" void kernel_launch(void* const* d_in, const int* in_sizes, int n_in,
                              void* d_out, int out_size)
{
    const float* x  = (const float*)d_in[0];
    const float* Wq = (const float*)d_in[1];
    const float* Wk = (const float*)d_in[2];
    const float* Wv = (const float*)d_in[3];
    const float* Er = (const float*)d_in[4];
    float* out = (float*)d_out;

    cudaFuncSetAttribute(proj_kernel,
                         cudaFuncAttributeMaxDynamicSharedMemorySize, PSMEM_BYTES);
    cudaFuncSetAttribute(attn_kernel,
                         cudaFuncAttributeMaxDynamicSharedMemorySize, ASMEM_BYTES);

    er_prep<<<(T_*H_ + 255)/256, 256>>>(Er);
    proj_kernel<<<dim3(256, 3), 256, PSMEM_BYTES>>>(x, Wq, Wk, Wv);
    attn_kernel<<<dim3(32, 16), 512, ASMEM_BYTES>>>(Er, out);
}